// round 1
// baseline (speedup 1.0000x reference)
#include <cuda_runtime.h>

#define SEQ    4096
#define DIM    1024
#define HEADS  16
#define DHEAD  64
#define QBETA  0.125f   // 1/sqrt(64)

// Scratch (allocation-free rule: __device__ globals)
__device__ float g_q[SEQ * DIM];
__device__ float g_k[SEQ * DIM];
__device__ float g_v[SEQ * DIM];
__device__ float g_att[SEQ * DIM];

// ---------------------------------------------------------------------------
// 64x64x(K=1024) fp32 GEMM tile: C[4096,1024] = alpha * A[4096,1024] @ B[1024,1024] (+bias)
// 256 threads (16x16), 4x4 microtile per thread.
// ---------------------------------------------------------------------------
__device__ __forceinline__ void gemm_tile_64(
    const float* __restrict__ A, const float* __restrict__ B,
    float* __restrict__ C, float alpha, const float* __restrict__ bias)
{
    __shared__ float As[64][65];   // [row][k]  (pad 65: scalar reads, broadcast per warp)
    __shared__ float Bs[64][68];   // [k][col]  (pad 68 keeps float4 alignment)

    const int tid = threadIdx.x;
    const int tx = tid & 15;
    const int ty = tid >> 4;
    const int row0 = blockIdx.y * 64;
    const int col0 = blockIdx.x * 64;

    float acc[4][4];
#pragma unroll
    for (int i = 0; i < 4; i++)
#pragma unroll
        for (int j = 0; j < 4; j++) acc[i][j] = 0.f;

    for (int k0 = 0; k0 < DIM; k0 += 64) {
#pragma unroll
        for (int r = 0; r < 4; r++) {
            const int arow = ty + r * 16;
            float4 av = *(const float4*)&A[(size_t)(row0 + arow) * DIM + k0 + tx * 4];
            As[arow][tx * 4 + 0] = av.x;
            As[arow][tx * 4 + 1] = av.y;
            As[arow][tx * 4 + 2] = av.z;
            As[arow][tx * 4 + 3] = av.w;
            float4 bv = *(const float4*)&B[(size_t)(k0 + arow) * DIM + col0 + tx * 4];
            *(float4*)&Bs[arow][tx * 4] = bv;
        }
        __syncthreads();
#pragma unroll
        for (int k = 0; k < 64; k++) {
            const float a0 = As[ty * 4 + 0][k];
            const float a1 = As[ty * 4 + 1][k];
            const float a2 = As[ty * 4 + 2][k];
            const float a3 = As[ty * 4 + 3][k];
            const float4 b = *(const float4*)&Bs[k][tx * 4];
            acc[0][0] += a0 * b.x; acc[0][1] += a0 * b.y; acc[0][2] += a0 * b.z; acc[0][3] += a0 * b.w;
            acc[1][0] += a1 * b.x; acc[1][1] += a1 * b.y; acc[1][2] += a1 * b.z; acc[1][3] += a1 * b.w;
            acc[2][0] += a2 * b.x; acc[2][1] += a2 * b.y; acc[2][2] += a2 * b.z; acc[2][3] += a2 * b.w;
            acc[3][0] += a3 * b.x; acc[3][1] += a3 * b.y; acc[3][2] += a3 * b.z; acc[3][3] += a3 * b.w;
        }
        __syncthreads();
    }

    float bx = 0.f, by = 0.f, bz = 0.f, bw = 0.f;
    if (bias) {
        bx = bias[col0 + tx * 4 + 0];
        by = bias[col0 + tx * 4 + 1];
        bz = bias[col0 + tx * 4 + 2];
        bw = bias[col0 + tx * 4 + 3];
    }
#pragma unroll
    for (int i = 0; i < 4; i++) {
        float4 o;
        o.x = acc[i][0] * alpha + bx;
        o.y = acc[i][1] * alpha + by;
        o.z = acc[i][2] * alpha + bz;
        o.w = acc[i][3] * alpha + bw;
        *(float4*)&C[(size_t)(row0 + ty * 4 + i) * DIM + col0 + tx * 4] = o;
    }
}

__global__ void __launch_bounds__(256) qkv_kernel(
    const float* __restrict__ x,
    const float* __restrict__ Wq,
    const float* __restrict__ Wk,
    const float* __restrict__ Wv)
{
    if (blockIdx.z == 0)      gemm_tile_64(x, Wq, g_q, QBETA, nullptr);
    else if (blockIdx.z == 1) gemm_tile_64(x, Wk, g_k, 1.f, nullptr);
    else                      gemm_tile_64(x, Wv, g_v, 1.f, nullptr);
}

__global__ void __launch_bounds__(256) out_kernel(
    const float* __restrict__ Wo,
    const float* __restrict__ bo,
    float* __restrict__ out)
{
    gemm_tile_64(g_att, Wo, out, 1.f, bo);
}

// ---------------------------------------------------------------------------
// Flash attention, causal, fp32. One block = (64 query rows, one head).
// 256 threads (16x16): each thread owns a 4x4 tile of S / O.
// Dynamic smem: Qs[64][65] | Kts[64][68] (transposed: [d][j]) | Vs[64][68] | Ps[64][65]
// ---------------------------------------------------------------------------
#define FLASH_SMEM_FLOATS (64 * 65 + 64 * 68 + 64 * 68 + 64 * 65)
#define FLASH_SMEM_BYTES  (FLASH_SMEM_FLOATS * 4)

__global__ void __launch_bounds__(256) flash_kernel()
{
    extern __shared__ float sm[];
    float (*Qs)[65]  = (float(*)[65])  sm;
    float (*Kts)[68] = (float(*)[68]) (sm + 64 * 65);
    float (*Vs)[68]  = (float(*)[68]) (sm + 64 * 65 + 64 * 68);
    float (*Ps)[65]  = (float(*)[65]) (sm + 64 * 65 + 2 * 64 * 68);

    const int tid = threadIdx.x;
    const int tx = tid & 15;
    const int ty = tid >> 4;
    const int h  = blockIdx.y;
    const int qt = blockIdx.x;
    const int hoff = h * DHEAD;

    // Load Q tile (already scaled by beta at projection time)
#pragma unroll
    for (int r = 0; r < 4; r++) {
        const int qrow = ty + r * 16;
        float4 qv = *(const float4*)&g_q[(size_t)(qt * 64 + qrow) * DIM + hoff + tx * 4];
        Qs[qrow][tx * 4 + 0] = qv.x;
        Qs[qrow][tx * 4 + 1] = qv.y;
        Qs[qrow][tx * 4 + 2] = qv.z;
        Qs[qrow][tx * 4 + 3] = qv.w;
    }

    float o[4][4];
    float m_i[4], l_i[4];
#pragma unroll
    for (int i = 0; i < 4; i++) {
        m_i[i] = -1e30f;
        l_i[i] = 0.f;
#pragma unroll
        for (int j = 0; j < 4; j++) o[i][j] = 0.f;
    }
    __syncthreads();

    for (int jt = 0; jt <= qt; jt++) {
        // Load K (transposed to [d][j]) and V ([j][d])
#pragma unroll
        for (int r = 0; r < 4; r++) {
            const int j = ty + r * 16;
            float4 kv = *(const float4*)&g_k[(size_t)(jt * 64 + j) * DIM + hoff + tx * 4];
            Kts[tx * 4 + 0][j] = kv.x;
            Kts[tx * 4 + 1][j] = kv.y;
            Kts[tx * 4 + 2][j] = kv.z;
            Kts[tx * 4 + 3][j] = kv.w;
            float4 vv = *(const float4*)&g_v[(size_t)(jt * 64 + j) * DIM + hoff + tx * 4];
            *(float4*)&Vs[j][tx * 4] = vv;
        }
        __syncthreads();

        // S = Q @ K^T  (4x4 per thread, k over d=64)
        float s[4][4];
#pragma unroll
        for (int i = 0; i < 4; i++)
#pragma unroll
            for (int j = 0; j < 4; j++) s[i][j] = 0.f;
#pragma unroll
        for (int d = 0; d < 64; d++) {
            const float a0 = Qs[ty * 4 + 0][d];
            const float a1 = Qs[ty * 4 + 1][d];
            const float a2 = Qs[ty * 4 + 2][d];
            const float a3 = Qs[ty * 4 + 3][d];
            const float4 kk = *(const float4*)&Kts[d][tx * 4];
            s[0][0] += a0 * kk.x; s[0][1] += a0 * kk.y; s[0][2] += a0 * kk.z; s[0][3] += a0 * kk.w;
            s[1][0] += a1 * kk.x; s[1][1] += a1 * kk.y; s[1][2] += a1 * kk.z; s[1][3] += a1 * kk.w;
            s[2][0] += a2 * kk.x; s[2][1] += a2 * kk.y; s[2][2] += a2 * kk.z; s[2][3] += a2 * kk.w;
            s[3][0] += a3 * kk.x; s[3][1] += a3 * kk.y; s[3][2] += a3 * kk.z; s[3][3] += a3 * kk.w;
        }

        // Causal mask (only the diagonal tile needs it)
        if (jt == qt) {
#pragma unroll
            for (int i = 0; i < 4; i++)
#pragma unroll
                for (int j = 0; j < 4; j++)
                    if (tx * 4 + j > ty * 4 + i) s[i][j] = -1e30f;
        }

        // Online softmax. Rows for a thread depend only on ty; the 16 lanes
        // (same ty) within a warp half share a row -> shfl_xor over {1,2,4,8}.
#pragma unroll
        for (int i = 0; i < 4; i++) {
            float rmax = fmaxf(fmaxf(s[i][0], s[i][1]), fmaxf(s[i][2], s[i][3]));
            rmax = fmaxf(rmax, __shfl_xor_sync(0xffffffffu, rmax, 1));
            rmax = fmaxf(rmax, __shfl_xor_sync(0xffffffffu, rmax, 2));
            rmax = fmaxf(rmax, __shfl_xor_sync(0xffffffffu, rmax, 4));
            rmax = fmaxf(rmax, __shfl_xor_sync(0xffffffffu, rmax, 8));
            const float mnew = fmaxf(m_i[i], rmax);
            const float corr = __expf(m_i[i] - mnew);
            m_i[i] = mnew;
            float rs = 0.f;
#pragma unroll
            for (int j = 0; j < 4; j++) {
                s[i][j] = __expf(s[i][j] - mnew);
                rs += s[i][j];
            }
            rs += __shfl_xor_sync(0xffffffffu, rs, 1);
            rs += __shfl_xor_sync(0xffffffffu, rs, 2);
            rs += __shfl_xor_sync(0xffffffffu, rs, 4);
            rs += __shfl_xor_sync(0xffffffffu, rs, 8);
            l_i[i] = l_i[i] * corr + rs;
#pragma unroll
            for (int j = 0; j < 4; j++) o[i][j] *= corr;
            Ps[ty * 4 + i][tx * 4 + 0] = s[i][0];
            Ps[ty * 4 + i][tx * 4 + 1] = s[i][1];
            Ps[ty * 4 + i][tx * 4 + 2] = s[i][2];
            Ps[ty * 4 + i][tx * 4 + 3] = s[i][3];
        }
        __syncthreads();

        // O += P @ V
#pragma unroll
        for (int j = 0; j < 64; j++) {
            const float p0 = Ps[ty * 4 + 0][j];
            const float p1 = Ps[ty * 4 + 1][j];
            const float p2 = Ps[ty * 4 + 2][j];
            const float p3 = Ps[ty * 4 + 3][j];
            const float4 vv = *(const float4*)&Vs[j][tx * 4];
            o[0][0] += p0 * vv.x; o[0][1] += p0 * vv.y; o[0][2] += p0 * vv.z; o[0][3] += p0 * vv.w;
            o[1][0] += p1 * vv.x; o[1][1] += p1 * vv.y; o[1][2] += p1 * vv.z; o[1][3] += p1 * vv.w;
            o[2][0] += p2 * vv.x; o[2][1] += p2 * vv.y; o[2][2] += p2 * vv.z; o[2][3] += p2 * vv.w;
            o[3][0] += p3 * vv.x; o[3][1] += p3 * vv.y; o[3][2] += p3 * vv.z; o[3][3] += p3 * vv.w;
        }
        __syncthreads();
    }

    // Normalize and write [n, h, d] layout
#pragma unroll
    for (int i = 0; i < 4; i++) {
        const float inv = 1.f / l_i[i];
        float4 ov;
        ov.x = o[i][0] * inv;
        ov.y = o[i][1] * inv;
        ov.z = o[i][2] * inv;
        ov.w = o[i][3] * inv;
        *(float4*)&g_att[(size_t)(qt * 64 + ty * 4 + i) * DIM + hoff + tx * 4] = ov;
    }
}

// ---------------------------------------------------------------------------
extern "C" void kernel_launch(void* const* d_in, const int* in_sizes, int n_in,
                              void* d_out, int out_size)
{
    const float* x  = (const float*)d_in[0];
    const float* Wq = (const float*)d_in[1];
    const float* Wk = (const float*)d_in[2];
    const float* Wv = (const float*)d_in[3];
    const float* Wo = (const float*)d_in[4];
    const float* bo = (const float*)d_in[5];
    float* out = (float*)d_out;

    cudaFuncSetAttribute(flash_kernel,
                         cudaFuncAttributeMaxDynamicSharedMemorySize,
                         FLASH_SMEM_BYTES);

    qkv_kernel<<<dim3(DIM / 64, SEQ / 64, 3), 256>>>(x, Wq, Wk, Wv);
    flash_kernel<<<dim3(SEQ / 64, HEADS), 256, FLASH_SMEM_BYTES>>>();
    out_kernel<<<dim3(DIM / 64, SEQ / 64), 256>>>(Wo, bo, out);
}

// round 3
// speedup vs baseline: 3.4915x; 3.4915x over previous
#include <cuda_runtime.h>
#include <cstdint>

#define SEQ    4096
#define DIM    1024
#define HEADS  16
#define DHEAD  64
#define QBETA  0.125f   // 1/sqrt(64)

// Scratch (allocation-free rule: __device__ globals)
__device__ float g_q[SEQ * DIM];
__device__ float g_k[SEQ * DIM];
__device__ float g_v[SEQ * DIM];
__device__ float g_att[SEQ * DIM];

// ---------------------------------------------------------------------------
// tf32 helpers
// ---------------------------------------------------------------------------
__device__ __forceinline__ unsigned f2tf(float x) {
    unsigned u;
    asm("cvt.rna.tf32.f32 %0, %1;" : "=r"(u) : "f"(x));
    return u;
}

__device__ __forceinline__ void mma_tf32(float* c,
                                         unsigned a0, unsigned a1, unsigned a2, unsigned a3,
                                         unsigned b0, unsigned b1) {
    asm volatile(
        "mma.sync.aligned.m16n8k8.row.col.f32.tf32.tf32.f32 "
        "{%0,%1,%2,%3},{%4,%5,%6,%7},{%8,%9},{%0,%1,%2,%3};"
        : "+f"(c[0]), "+f"(c[1]), "+f"(c[2]), "+f"(c[3])
        : "r"(a0), "r"(a1), "r"(a2), "r"(a3), "r"(b0), "r"(b1));
}

// ---------------------------------------------------------------------------
// tf32 GEMM: C[4096,N=1024] = alpha * A[4096,1024] @ B[1024,1024] (+bias)
// Block tile 128x64, K-step 32, 256 threads = 8 warps (4x2), warp tile 32x32.
// Fragment-gather LDS conflict-free: A ld=36 (4g+t spans banks),
//                                    B ld=72 (8t+g spans banks).
// ---------------------------------------------------------------------------
#define GA_LD 36
#define GB_LD 72

__device__ __forceinline__ void gemm_tf32_tile(
    const float* __restrict__ A, const float* __restrict__ B,
    float* __restrict__ C, float alpha, const float* __restrict__ bias)
{
    __shared__ unsigned As[128 * GA_LD];
    __shared__ unsigned Bs[32 * GB_LD];

    const int tid  = threadIdx.x;
    const int lane = tid & 31;
    const int warp = tid >> 5;
    const int g = lane >> 2;   // group id (row within fragment)
    const int t = lane & 3;    // thread-in-group (col within fragment)
    const int wm = warp & 3;   // warp row (x32)
    const int wn = warp >> 2;  // warp col (x32)
    const int row0 = blockIdx.y * 128;
    const int col0 = blockIdx.x * 64;

    float acc[2][4][4];
#pragma unroll
    for (int mi = 0; mi < 2; mi++)
#pragma unroll
        for (int ni = 0; ni < 4; ni++)
#pragma unroll
            for (int e = 0; e < 4; e++) acc[mi][ni][e] = 0.f;

    for (int k0 = 0; k0 < DIM; k0 += 32) {
        // stage A 128x32 (pre-converted to tf32 bits)
#pragma unroll
        for (int p = 0; p < 4; p++) {
            const int r = (tid >> 3) + p * 32;
            const int c = (tid & 7) * 4;
            float4 v = *(const float4*)&A[(size_t)(row0 + r) * DIM + k0 + c];
            unsigned* d = &As[r * GA_LD + c];
            d[0] = f2tf(v.x); d[1] = f2tf(v.y); d[2] = f2tf(v.z); d[3] = f2tf(v.w);
        }
        // stage B 32x64
#pragma unroll
        for (int p = 0; p < 2; p++) {
            const int r = (tid >> 4) + p * 16;
            const int c = (tid & 15) * 4;
            float4 v = *(const float4*)&B[(size_t)(k0 + r) * DIM + col0 + c];
            unsigned* d = &Bs[r * GB_LD + c];
            d[0] = f2tf(v.x); d[1] = f2tf(v.y); d[2] = f2tf(v.z); d[3] = f2tf(v.w);
        }
        __syncthreads();

#pragma unroll
        for (int kk = 0; kk < 4; kk++) {
            unsigned a[2][4];
#pragma unroll
            for (int mi = 0; mi < 2; mi++) {
                const int rb = wm * 32 + mi * 16;
                a[mi][0] = As[(rb + g)     * GA_LD + kk * 8 + t];
                a[mi][1] = As[(rb + g + 8) * GA_LD + kk * 8 + t];
                a[mi][2] = As[(rb + g)     * GA_LD + kk * 8 + t + 4];
                a[mi][3] = As[(rb + g + 8) * GA_LD + kk * 8 + t + 4];
            }
#pragma unroll
            for (int ni = 0; ni < 4; ni++) {
                const unsigned b0 = Bs[(kk * 8 + t)     * GB_LD + wn * 32 + ni * 8 + g];
                const unsigned b1 = Bs[(kk * 8 + t + 4) * GB_LD + wn * 32 + ni * 8 + g];
                mma_tf32(acc[0][ni], a[0][0], a[0][1], a[0][2], a[0][3], b0, b1);
                mma_tf32(acc[1][ni], a[1][0], a[1][1], a[1][2], a[1][3], b0, b1);
            }
        }
        __syncthreads();
    }

    // epilogue
#pragma unroll
    for (int mi = 0; mi < 2; mi++) {
        const int rb = row0 + wm * 32 + mi * 16;
#pragma unroll
        for (int ni = 0; ni < 4; ni++) {
            const int cb = col0 + wn * 32 + ni * 8 + 2 * t;
            float bv0 = 0.f, bv1 = 0.f;
            if (bias) { bv0 = bias[cb]; bv1 = bias[cb + 1]; }
            float2 o0 = { acc[mi][ni][0] * alpha + bv0, acc[mi][ni][1] * alpha + bv1 };
            float2 o1 = { acc[mi][ni][2] * alpha + bv0, acc[mi][ni][3] * alpha + bv1 };
            *(float2*)&C[(size_t)(rb + g)     * DIM + cb] = o0;
            *(float2*)&C[(size_t)(rb + g + 8) * DIM + cb] = o1;
        }
    }
}

__global__ void __launch_bounds__(256) qkv_kernel(
    const float* __restrict__ x,
    const float* __restrict__ Wq,
    const float* __restrict__ Wk,
    const float* __restrict__ Wv)
{
    if (blockIdx.z == 0)      gemm_tf32_tile(x, Wq, g_q, QBETA, nullptr);
    else if (blockIdx.z == 1) gemm_tf32_tile(x, Wk, g_k, 1.f, nullptr);
    else                      gemm_tf32_tile(x, Wv, g_v, 1.f, nullptr);
}

__global__ void __launch_bounds__(256) out_kernel(
    const float* __restrict__ Wo,
    const float* __restrict__ bo,
    float* __restrict__ out)
{
    gemm_tf32_tile(g_att, Wo, out, 1.f, bo);
}

// ---------------------------------------------------------------------------
// Flash attention, causal, tf32 mma. One block = (64 q-rows, one head),
// 128 threads = 4 warps, each warp owns 16 q-rows (one m16 fragment row).
// smem leading dims: Qs/Ks/Ps ld=68 (A-frag & K^T-frag pattern: 4g+t),
//                    Vs ld=72 (V-frag pattern: 8t+g). All conflict-free.
// ---------------------------------------------------------------------------
#define FL_QLD 68
#define FL_KLD 68
#define FL_VLD 72
#define FL_PLD 68
#define OFF_Q 0
#define OFF_K (OFF_Q + 64 * FL_QLD)
#define OFF_V (OFF_K + 64 * FL_KLD)
#define OFF_P (OFF_V + 64 * FL_VLD)
#define FL_SMEM_UINTS (OFF_P + 64 * FL_PLD)
#define FL_SMEM_BYTES (FL_SMEM_UINTS * 4)

__global__ void __launch_bounds__(128) flash_kernel()
{
    extern __shared__ unsigned sm[];
    unsigned* Qs = sm + OFF_Q;
    unsigned* Ks = sm + OFF_K;
    unsigned* Vs = sm + OFF_V;
    unsigned* Ps = sm + OFF_P;

    const int tid  = threadIdx.x;
    const int lane = tid & 31;
    const int warp = tid >> 5;
    const int g = lane >> 2;
    const int t = lane & 3;
    const int h  = blockIdx.y;
    const int qt = gridDim.x - 1 - blockIdx.x;   // heaviest q-tiles first
    const int hoff = h * DHEAD;
    const int rb = warp * 16;                    // warp's local row base

    // stage Q (beta already folded in at projection)
    {
        const int r = tid >> 1, cb = (tid & 1) * 32;
        const float4* src = (const float4*)&g_q[(size_t)(qt * 64 + r) * DIM + hoff + cb];
#pragma unroll
        for (int i = 0; i < 8; i++) {
            float4 v = src[i];
            unsigned* d = &Qs[r * FL_QLD + cb + i * 4];
            d[0] = f2tf(v.x); d[1] = f2tf(v.y); d[2] = f2tf(v.z); d[3] = f2tf(v.w);
        }
    }

    float o[8][4];
#pragma unroll
    for (int ni = 0; ni < 8; ni++)
#pragma unroll
        for (int e = 0; e < 4; e++) o[ni][e] = 0.f;
    float m0 = -1e30f, m1 = -1e30f, l0 = 0.f, l1 = 0.f;
    __syncthreads();

    for (int jt = 0; jt <= qt; jt++) {
        // stage K and V tiles
        {
            const int r = tid >> 1, cb = (tid & 1) * 32;
            const float4* ks = (const float4*)&g_k[(size_t)(jt * 64 + r) * DIM + hoff + cb];
            const float4* vs = (const float4*)&g_v[(size_t)(jt * 64 + r) * DIM + hoff + cb];
#pragma unroll
            for (int i = 0; i < 8; i++) {
                float4 v = ks[i];
                unsigned* d = &Ks[r * FL_KLD + cb + i * 4];
                d[0] = f2tf(v.x); d[1] = f2tf(v.y); d[2] = f2tf(v.z); d[3] = f2tf(v.w);
                float4 w = vs[i];
                unsigned* e = &Vs[r * FL_VLD + cb + i * 4];
                e[0] = f2tf(w.x); e[1] = f2tf(w.y); e[2] = f2tf(w.z); e[3] = f2tf(w.w);
            }
        }
        __syncthreads();

        // S = Q @ K^T   (m16 x n64, k=64)
        float s[8][4];
#pragma unroll
        for (int ni = 0; ni < 8; ni++)
#pragma unroll
            for (int e = 0; e < 4; e++) s[ni][e] = 0.f;

#pragma unroll
        for (int kk = 0; kk < 8; kk++) {
            const unsigned a0 = Qs[(rb + g)     * FL_QLD + kk * 8 + t];
            const unsigned a1 = Qs[(rb + g + 8) * FL_QLD + kk * 8 + t];
            const unsigned a2 = Qs[(rb + g)     * FL_QLD + kk * 8 + t + 4];
            const unsigned a3 = Qs[(rb + g + 8) * FL_QLD + kk * 8 + t + 4];
#pragma unroll
            for (int ni = 0; ni < 8; ni++) {
                const unsigned b0 = Ks[(ni * 8 + g) * FL_KLD + kk * 8 + t];
                const unsigned b1 = Ks[(ni * 8 + g) * FL_KLD + kk * 8 + t + 4];
                mma_tf32(s[ni], a0, a1, a2, a3, b0, b1);
            }
        }

        // causal mask (diagonal tile only)
        if (jt == qt) {
            const int li0 = rb + g, li1 = li0 + 8;
#pragma unroll
            for (int ni = 0; ni < 8; ni++) {
                const int j0 = ni * 8 + 2 * t, j1 = j0 + 1;
                if (j0 > li0) s[ni][0] = -1e30f;
                if (j1 > li0) s[ni][1] = -1e30f;
                if (j0 > li1) s[ni][2] = -1e30f;
                if (j1 > li1) s[ni][3] = -1e30f;
            }
        }

        // online softmax (rows g and g+8; 4 lanes per row -> shfl_xor 1,2)
        float rm0 = -1e30f, rm1 = -1e30f;
#pragma unroll
        for (int ni = 0; ni < 8; ni++) {
            rm0 = fmaxf(rm0, fmaxf(s[ni][0], s[ni][1]));
            rm1 = fmaxf(rm1, fmaxf(s[ni][2], s[ni][3]));
        }
        rm0 = fmaxf(rm0, __shfl_xor_sync(0xffffffffu, rm0, 1));
        rm0 = fmaxf(rm0, __shfl_xor_sync(0xffffffffu, rm0, 2));
        rm1 = fmaxf(rm1, __shfl_xor_sync(0xffffffffu, rm1, 1));
        rm1 = fmaxf(rm1, __shfl_xor_sync(0xffffffffu, rm1, 2));

        const float mn0 = fmaxf(m0, rm0), mn1 = fmaxf(m1, rm1);
        const float corr0 = __expf(m0 - mn0), corr1 = __expf(m1 - mn1);
        m0 = mn0; m1 = mn1;

        float rs0 = 0.f, rs1 = 0.f;
#pragma unroll
        for (int ni = 0; ni < 8; ni++) {
            s[ni][0] = __expf(s[ni][0] - mn0);
            s[ni][1] = __expf(s[ni][1] - mn0);
            s[ni][2] = __expf(s[ni][2] - mn1);
            s[ni][3] = __expf(s[ni][3] - mn1);
            rs0 += s[ni][0] + s[ni][1];
            rs1 += s[ni][2] + s[ni][3];
            Ps[(rb + g)     * FL_PLD + ni * 8 + 2 * t]     = f2tf(s[ni][0]);
            Ps[(rb + g)     * FL_PLD + ni * 8 + 2 * t + 1] = f2tf(s[ni][1]);
            Ps[(rb + g + 8) * FL_PLD + ni * 8 + 2 * t]     = f2tf(s[ni][2]);
            Ps[(rb + g + 8) * FL_PLD + ni * 8 + 2 * t + 1] = f2tf(s[ni][3]);
        }
        rs0 += __shfl_xor_sync(0xffffffffu, rs0, 1);
        rs0 += __shfl_xor_sync(0xffffffffu, rs0, 2);
        rs1 += __shfl_xor_sync(0xffffffffu, rs1, 1);
        rs1 += __shfl_xor_sync(0xffffffffu, rs1, 2);
        l0 = l0 * corr0 + rs0;
        l1 = l1 * corr1 + rs1;

#pragma unroll
        for (int ni = 0; ni < 8; ni++) {
            o[ni][0] *= corr0; o[ni][1] *= corr0;
            o[ni][2] *= corr1; o[ni][3] *= corr1;
        }
        __syncwarp();   // Ps write -> read is warp-local

        // O += P @ V   (m16 x n64, k=64)
#pragma unroll
        for (int kk = 0; kk < 8; kk++) {
            const unsigned a0 = Ps[(rb + g)     * FL_PLD + kk * 8 + t];
            const unsigned a1 = Ps[(rb + g + 8) * FL_PLD + kk * 8 + t];
            const unsigned a2 = Ps[(rb + g)     * FL_PLD + kk * 8 + t + 4];
            const unsigned a3 = Ps[(rb + g + 8) * FL_PLD + kk * 8 + t + 4];
#pragma unroll
            for (int ni = 0; ni < 8; ni++) {
                const unsigned b0 = Vs[(kk * 8 + t)     * FL_VLD + ni * 8 + g];
                const unsigned b1 = Vs[(kk * 8 + t + 4) * FL_VLD + ni * 8 + g];
                mma_tf32(o[ni], a0, a1, a2, a3, b0, b1);
            }
        }
        __syncthreads();   // protect K/V/P tiles before next stage
    }

    // normalize + write [n, h*d] layout
    const float inv0 = 1.f / l0, inv1 = 1.f / l1;
    const int row = qt * 64 + rb;
#pragma unroll
    for (int ni = 0; ni < 8; ni++) {
        const int cb = hoff + ni * 8 + 2 * t;
        float2 v0 = { o[ni][0] * inv0, o[ni][1] * inv0 };
        float2 v1 = { o[ni][2] * inv1, o[ni][3] * inv1 };
        *(float2*)&g_att[(size_t)(row + g)     * DIM + cb] = v0;
        *(float2*)&g_att[(size_t)(row + g + 8) * DIM + cb] = v1;
    }
}

// ---------------------------------------------------------------------------
extern "C" void kernel_launch(void* const* d_in, const int* in_sizes, int n_in,
                              void* d_out, int out_size)
{
    const float* x  = (const float*)d_in[0];
    const float* Wq = (const float*)d_in[1];
    const float* Wk = (const float*)d_in[2];
    const float* Wv = (const float*)d_in[3];
    const float* Wo = (const float*)d_in[4];
    const float* bo = (const float*)d_in[5];
    float* out = (float*)d_out;

    cudaFuncSetAttribute(flash_kernel,
                         cudaFuncAttributeMaxDynamicSharedMemorySize,
                         FL_SMEM_BYTES);

    qkv_kernel<<<dim3(DIM / 64, SEQ / 128, 3), 256>>>(x, Wq, Wk, Wv);
    flash_kernel<<<dim3(SEQ / 64, HEADS), 128, FL_SMEM_BYTES>>>();
    out_kernel<<<dim3(DIM / 64, SEQ / 128), 256>>>(Wo, bo, out);
}